// round 8
// baseline (speedup 1.0000x reference)
#include <cuda_runtime.h>
#include <cuda_bf16.h>
#include <math.h>
#include <stdint.h>

#define BB 8
#define SS 2048
#define DD 1024
#define HH 64

// Scratch.
__device__ float g_Q[BB * SS * HH];                 // fp32 Q
__device__ float g_V[BB * SS * HH];                 // fp32 V (input to prep_vt)
__device__ uint32_t g_Khp[BB * SS * 32];            // K hi, bf16x2 pairs along h
__device__ uint32_t g_Klp[BB * SS * 32];            // K lo
__device__ uint32_t g_Vthp[BB * 64 * 1024];         // V^T hi: [b][h][s/2] pairs along s
__device__ uint32_t g_Vtlp[BB * 64 * 1024];         // V^T lo
__device__ __nv_bfloat16 g_Bh[192 * 1024];          // weights hi  [n][k]
__device__ __nv_bfloat16 g_Bl[192 * 1024];          // weights lo

// ---------------------------------------------------------------------------
// Truncation-based fp32 -> bf16 hi/lo split for a pair of floats.
// ---------------------------------------------------------------------------
__device__ __forceinline__ void tsplit2(float a, float b, uint32_t& hi, uint32_t& lo) {
    uint32_t ia = __float_as_uint(a), ib = __float_as_uint(b);
    hi = __byte_perm(ia, ib, 0x7632);
    float ra = a - __uint_as_float(ia & 0xFFFF0000u);
    float rb = b - __uint_as_float(ib & 0xFFFF0000u);
    asm("cvt.rn.bf16x2.f32 %0, %1, %2;" : "=r"(lo) : "f"(rb), "f"(ra));
}

// Fast exp2 for x <= 0 (clamped at -80): FMA/ALU pipes only, no MUFU.
__device__ __forceinline__ float exp2_fast(float x) {
    x = fmaxf(x, -80.0f);
    float z = x + 12582912.0f;
    float n = z - 12582912.0f;
    float f = x - n;
    float p =            1.3333558e-3f;
    p = fmaf(p, f, 9.6181291e-3f);
    p = fmaf(p, f, 5.5504109e-2f);
    p = fmaf(p, f, 2.4022650e-1f);
    p = fmaf(p, f, 6.9314718e-1f);
    p = fmaf(p, f, 1.0f);
    int e = __float_as_int(z);
    float sc = __int_as_float((e + (127 - 0x4B400000)) << 23);
    return p * sc;
}

__device__ __forceinline__ void mma_bf16(float c[4],
                                         uint32_t a0, uint32_t a1, uint32_t a2, uint32_t a3,
                                         uint32_t b0, uint32_t b1) {
    asm volatile(
        "mma.sync.aligned.m16n8k16.row.col.f32.bf16.bf16.f32 "
        "{%0,%1,%2,%3}, {%4,%5,%6,%7}, {%8,%9}, {%0,%1,%2,%3};"
        : "+f"(c[0]), "+f"(c[1]), "+f"(c[2]), "+f"(c[3])
        : "r"(a0), "r"(a1), "r"(a2), "r"(a3), "r"(b0), "r"(b1));
}

__device__ __forceinline__ uint32_t lds32(const __nv_bfloat16* p) {
    return *(const uint32_t*)p;
}

__device__ __forceinline__ uint32_t smem_u32(const void* p) {
    uint32_t a;
    asm("{ .reg .u64 t; cvta.to.shared.u64 t, %1; cvt.u32.u64 %0, t; }"
        : "=r"(a) : "l"(p));
    return a;
}
__device__ __forceinline__ void cp16(uint32_t saddr, const void* g) {
    asm volatile("cp.async.cg.shared.global [%0], [%1], 16;" :: "r"(saddr), "l"(g));
}
#define CP_COMMIT() asm volatile("cp.async.commit_group;" ::: "memory")
#define CP_WAIT0()  asm volatile("cp.async.wait_group 0;" ::: "memory")

// ---------------------------------------------------------------------------
// Kernel 0: split weights W[k][n] fp32 -> g_Bh/g_Bl[n_global][k] bf16.
// ---------------------------------------------------------------------------
__global__ void prep_w(const float* __restrict__ Wq,
                       const float* __restrict__ Wk,
                       const float* __restrict__ Wv)
{
    int i = blockIdx.x * blockDim.x + threadIdx.x;
    int n = i >> 10;
    int k = i & 1023;
    int m = n >> 6;
    int col = n & 63;
    const float* W = (m == 0) ? Wq : (m == 1) ? Wk : Wv;
    float w = W[k * 64 + col];
    __nv_bfloat16 h = __float2bfloat16(w);
    float lo = w - __bfloat162float(h);
    g_Bh[(size_t)n * 1024 + k] = h;
    g_Bl[(size_t)n * 1024 + k] = __float2bfloat16(lo);
}

// ---------------------------------------------------------------------------
// Kernel 1: QKV projection. M-tile 64 -> grid 256 CTAs (all SMs busy).
// 256 threads, warp grid 4(M) x 2(N): warp tile 16 x 96.
// ---------------------------------------------------------------------------
#define APITCH 36
#define BPITCH 36

__global__ __launch_bounds__(256) void qkv_mma(const float* __restrict__ x)
{
    __shared__ __align__(16) __nv_bfloat16 Ah[64 * APITCH];
    __shared__ __align__(16) __nv_bfloat16 Al[64 * APITCH];
    __shared__ __align__(16) __nv_bfloat16 Bh[192 * BPITCH];
    __shared__ __align__(16) __nv_bfloat16 Bl[192 * BPITCH];

    const int tid = threadIdx.x;
    const int wid = tid >> 5;
    const int lane = tid & 31;
    const int grow = lane >> 2;
    const int tg = lane & 3;
    const int warp_m = wid & 3;      // 16 rows each
    const int warp_n = wid >> 2;     // 96 cols each
    const int row0 = blockIdx.x * 64;

    float acc[12][4] = {};

    for (int k0 = 0; k0 < DD; k0 += 32) {
        // ---- A: x fp32 [64 x 32] -> split hi/lo bf16 (2 float4 per thread).
        #pragma unroll
        for (int i = 0; i < 2; i++) {
            int idx = tid + (i << 8);        // 0..511
            int r = idx >> 3;
            int c4 = idx & 7;
            float4 f = *(const float4*)(x + (size_t)(row0 + r) * DD + k0 + c4 * 4);
            uint32_t h01, l01, h23, l23;
            tsplit2(f.x, f.y, h01, l01);
            tsplit2(f.z, f.w, h23, l23);
            int off = r * APITCH + c4 * 4;
            *(uint2*)&Ah[off] = make_uint2(h01, h23);
            *(uint2*)&Al[off] = make_uint2(l01, l23);
        }
        // ---- B: [192 x 32] bf16 hi/lo (3 rows' worth per thread).
        #pragma unroll
        for (int i = 0; i < 3; i++) {
            int idx = tid + (i << 8);
            int r = idx >> 2;
            int q = idx & 3;
            int off = r * BPITCH + q * 8;
            uint4 vh = *(const uint4*)(g_Bh + (size_t)r * 1024 + k0 + q * 8);
            uint4 vl = *(const uint4*)(g_Bl + (size_t)r * 1024 + k0 + q * 8);
            *(uint2*)&Bh[off]     = make_uint2(vh.x, vh.y);
            *(uint2*)&Bh[off + 4] = make_uint2(vh.z, vh.w);
            *(uint2*)&Bl[off]     = make_uint2(vl.x, vl.y);
            *(uint2*)&Bl[off + 4] = make_uint2(vl.z, vl.w);
        }
        __syncthreads();

        #pragma unroll
        for (int ks = 0; ks < 2; ks++) {
            const int kofs = ks * 16 + tg * 2;
            int rb = (warp_m * 16 + grow) * APITCH + kofs;
            uint32_t a0h = lds32(Ah + rb);
            uint32_t a1h = lds32(Ah + rb + 8 * APITCH);
            uint32_t a2h = lds32(Ah + rb + 8);
            uint32_t a3h = lds32(Ah + rb + 8 * APITCH + 8);
            uint32_t a0l = lds32(Al + rb);
            uint32_t a1l = lds32(Al + rb + 8 * APITCH);
            uint32_t a2l = lds32(Al + rb + 8);
            uint32_t a3l = lds32(Al + rb + 8 * APITCH + 8);
            #pragma unroll
            for (int nt = 0; nt < 12; nt++) {
                int cb = (warp_n * 96 + nt * 8 + grow) * BPITCH + kofs;
                uint32_t bh0 = lds32(Bh + cb);
                uint32_t bh1 = lds32(Bh + cb + 8);
                uint32_t bl0 = lds32(Bl + cb);
                uint32_t bl1 = lds32(Bl + cb + 8);
                mma_bf16(acc[nt], a0h, a1h, a2h, a3h, bh0, bh1);
                mma_bf16(acc[nt], a0h, a1h, a2h, a3h, bl0, bl1);
                mma_bf16(acc[nt], a0l, a1l, a2l, a3l, bh0, bh1);
            }
        }
        __syncthreads();
    }

    // Epilogue: Q,V fp32; K split once into bf16 hi/lo pair arrays.
    int r = row0 + warp_m * 16 + grow;
    #pragma unroll
    for (int nt = 0; nt < 12; nt++) {
        int col = warp_n * 96 + nt * 8 + tg * 2;
        int mat = col >> 6;
        int c = col & 63;
        if (mat == 1) {
            uint32_t h0, l0, h1, l1;
            tsplit2(acc[nt][0], acc[nt][1], h0, l0);
            tsplit2(acc[nt][2], acc[nt][3], h1, l1);
            int pidx = c >> 1;
            g_Khp[(size_t)r * 32 + pidx] = h0;
            g_Klp[(size_t)r * 32 + pidx] = l0;
            g_Khp[(size_t)(r + 8) * 32 + pidx] = h1;
            g_Klp[(size_t)(r + 8) * 32 + pidx] = l1;
        } else {
            float* dst = (mat == 0) ? g_Q : g_V;
            *(float2*)(dst + (size_t)r * 64 + c) =
                make_float2(acc[nt][0], acc[nt][1]);
            *(float2*)(dst + (size_t)(r + 8) * 64 + c) =
                make_float2(acc[nt][2], acc[nt][3]);
        }
    }
}

// ---------------------------------------------------------------------------
// Kernel 1b: transpose + split V once.
// ---------------------------------------------------------------------------
__global__ __launch_bounds__(256) void prep_vt()
{
    __shared__ float vt[64 * 65];
    const int tid = threadIdx.x;
    const int s0 = blockIdx.x * 64;
    const int b  = blockIdx.y;

    #pragma unroll
    for (int i = 0; i < 4; i++) {
        int idx = tid + (i << 8);
        int r = idx >> 4;
        int c4 = (idx & 15) << 2;
        float4 f = *(const float4*)(g_V + (size_t)(b * SS + s0 + r) * 64 + c4);
        vt[r * 65 + c4 + 0] = f.x;  vt[r * 65 + c4 + 1] = f.y;
        vt[r * 65 + c4 + 2] = f.z;  vt[r * 65 + c4 + 3] = f.w;
    }
    __syncthreads();

    #pragma unroll
    for (int i = 0; i < 8; i++) {
        int idx = tid + (i << 8);
        int h  = idx >> 5;
        int sp = idx & 31;
        float v0 = vt[(sp * 2 + 0) * 65 + h];
        float v1 = vt[(sp * 2 + 1) * 65 + h];
        uint32_t hi, lo;
        tsplit2(v0, v1, hi, lo);
        size_t o = (size_t)(b * 64 + h) * 1024 + (s0 >> 1) + sp;
        g_Vthp[o] = hi;
        g_Vtlp[o] = lo;
    }
}

// ---------------------------------------------------------------------------
// Kernel 2: causal flash attention, cp.async double-buffered K/V pipeline.
// Dynamic smem: 2 stages x {Kh,Kl,Vth,Vtl}[64 x 72] bf16 = 73728 B.
// One wait_group + one __syncthreads per kb iteration; next tile streams in
// during the MMAs. qb = 31 - bx so long CTAs launch first.
// ---------------------------------------------------------------------------
#define KPITCH 72
#define STAGE_BYTES (4 * 64 * KPITCH * 2)   // 36864
#define ARR_BYTES   (64 * KPITCH * 2)       // 9216
#define ATTN_SMEM   (2 * STAGE_BYTES)
#define SCL 0.18033688011112042f            /* 0.125 * log2(e) */

__global__ __launch_bounds__(128) void attn_mma(float* __restrict__ Out)
{
    extern __shared__ __align__(16) char smc[];
    const uint32_t sb = smem_u32(smc);

    const int tid = threadIdx.x;
    const int wm = tid >> 5;
    const int lane = tid & 31;
    const int grow = lane >> 2;
    const int tg = lane & 3;
    const int qb = 31 - blockIdx.x;      // long CTAs first
    const int b  = blockIdx.y;

    // Per-thread cp.async slot (same for every tile).
    const int cr = tid >> 3;             // 0..15 : row group
    const int cq = tid & 7;              // 0..7  : 16B column
    const uint32_t khp_base = (size_t)0; // silence unused warnings pattern

    // Issue one tile's 16 cp.async transfers into stage st.
    auto issue_tile = [&](int kb, int st) {
        uint32_t s0 = sb + st * STAGE_BYTES;
        const uint32_t* Khg = g_Khp + (size_t)(b * SS + kb * 64) * 32;
        const uint32_t* Klg = g_Klp + (size_t)(b * SS + kb * 64) * 32;
        const uint32_t* Vhg = g_Vthp + (size_t)b * 64 * 1024 + kb * 32;
        const uint32_t* Vlg = g_Vtlp + (size_t)b * 64 * 1024 + kb * 32;
        #pragma unroll
        for (int i = 0; i < 4; i++) {
            int r = cr + i * 16;         // 0..63
            cp16(s0 + 0 * ARR_BYTES + r * 144 + cq * 16, Khg + r * 32 + cq * 4);
            cp16(s0 + 1 * ARR_BYTES + r * 144 + cq * 16, Klg + r * 32 + cq * 4);
            cp16(s0 + 2 * ARR_BYTES + r * 144 + cq * 16, Vhg + (size_t)r * 1024 + cq * 4);
            cp16(s0 + 3 * ARR_BYTES + r * 144 + cq * 16, Vlg + (size_t)r * 1024 + cq * 4);
        }
        CP_COMMIT();
    };
    (void)khp_base;

    const float* Qg = g_Q + (size_t)(b * SS + qb * 64 + wm * 16) * HH;

    // Hoist Q fragments.
    uint32_t qh[4][4], ql[4][4];
    #pragma unroll
    for (int kt = 0; kt < 4; kt++) {
        float2 v00 = *(const float2*)(Qg + grow * HH + kt * 16 + tg * 2);
        float2 v10 = *(const float2*)(Qg + (grow + 8) * HH + kt * 16 + tg * 2);
        float2 v01 = *(const float2*)(Qg + grow * HH + kt * 16 + tg * 2 + 8);
        float2 v11 = *(const float2*)(Qg + (grow + 8) * HH + kt * 16 + tg * 2 + 8);
        tsplit2(v00.x, v00.y, qh[kt][0], ql[kt][0]);
        tsplit2(v10.x, v10.y, qh[kt][1], ql[kt][1]);
        tsplit2(v01.x, v01.y, qh[kt][2], ql[kt][2]);
        tsplit2(v11.x, v11.y, qh[kt][3], ql[kt][3]);
    }

    issue_tile(0, 0);

    float o[8][4] = {};
    float m0 = -1e30f, m1 = -1e30f, l0 = 0.0f, l1 = 0.0f;
    const int qr0 = qb * 64 + wm * 16 + grow;

    for (int kb = 0; kb <= qb; kb++) {
        CP_WAIT0();
        __syncthreads();
        if (kb < qb) issue_tile(kb + 1, (kb + 1) & 1);

        const uint32_t s0 = sb + (kb & 1) * STAGE_BYTES;
        const __nv_bfloat16* Kh  = (const __nv_bfloat16*)(smc + (kb & 1) * STAGE_BYTES);
        const __nv_bfloat16* Kl  = Kh  + 64 * KPITCH;
        const __nv_bfloat16* Vth = Kl  + 64 * KPITCH;
        const __nv_bfloat16* Vtl = Vth + 64 * KPITCH;
        (void)s0;

        // ---- S = Q K^T (3-term split).
        float s[8][4] = {};
        #pragma unroll
        for (int nt = 0; nt < 8; nt++) {
            #pragma unroll
            for (int kt = 0; kt < 4; kt++) {
                int cb = (nt * 8 + grow) * KPITCH + kt * 16 + tg * 2;
                uint32_t bh0 = lds32(Kh + cb), bh1 = lds32(Kh + cb + 8);
                uint32_t bl0 = lds32(Kl + cb), bl1 = lds32(Kl + cb + 8);
                mma_bf16(s[nt], qh[kt][0], qh[kt][1], qh[kt][2], qh[kt][3], bh0, bh1);
                mma_bf16(s[nt], qh[kt][0], qh[kt][1], qh[kt][2], qh[kt][3], bl0, bl1);
                mma_bf16(s[nt], ql[kt][0], ql[kt][1], ql[kt][2], ql[kt][3], bh0, bh1);
            }
        }

        // ---- scale + causal mask.
        if (kb == qb) {
            #pragma unroll
            for (int nt = 0; nt < 8; nt++) {
                int kc = kb * 64 + nt * 8 + tg * 2;
                s[nt][0] = (kc     > qr0)     ? -1e30f : s[nt][0] * SCL;
                s[nt][1] = (kc + 1 > qr0)     ? -1e30f : s[nt][1] * SCL;
                s[nt][2] = (kc     > qr0 + 8) ? -1e30f : s[nt][2] * SCL;
                s[nt][3] = (kc + 1 > qr0 + 8) ? -1e30f : s[nt][3] * SCL;
            }
        } else {
            #pragma unroll
            for (int nt = 0; nt < 8; nt++) {
                s[nt][0] *= SCL; s[nt][1] *= SCL;
                s[nt][2] *= SCL; s[nt][3] *= SCL;
            }
        }

        // ---- online softmax (base-2).
        float mx0 = -1e30f, mx1 = -1e30f;
        #pragma unroll
        for (int nt = 0; nt < 8; nt++) {
            mx0 = fmaxf(mx0, fmaxf(s[nt][0], s[nt][1]));
            mx1 = fmaxf(mx1, fmaxf(s[nt][2], s[nt][3]));
        }
        mx0 = fmaxf(mx0, __shfl_xor_sync(0xffffffffu, mx0, 1));
        mx0 = fmaxf(mx0, __shfl_xor_sync(0xffffffffu, mx0, 2));
        mx1 = fmaxf(mx1, __shfl_xor_sync(0xffffffffu, mx1, 1));
        mx1 = fmaxf(mx1, __shfl_xor_sync(0xffffffffu, mx1, 2));
        float nm0 = fmaxf(m0, mx0), nm1 = fmaxf(m1, mx1);
        float a0 = exp2_fast(m0 - nm0), a1 = exp2_fast(m1 - nm1);
        m0 = nm0; m1 = nm1;

        float rs0 = 0.0f, rs1 = 0.0f;
        #pragma unroll
        for (int nt = 0; nt < 8; nt++) {
            float p0 = exp2_fast(s[nt][0] - nm0);
            float p1 = exp2_fast(s[nt][1] - nm0);
            float p2 = exp2_fast(s[nt][2] - nm1);
            float p3 = exp2_fast(s[nt][3] - nm1);
            s[nt][0] = p0; s[nt][1] = p1; s[nt][2] = p2; s[nt][3] = p3;
            rs0 += p0 + p1;
            rs1 += p2 + p3;
        }
        rs0 += __shfl_xor_sync(0xffffffffu, rs0, 1);
        rs0 += __shfl_xor_sync(0xffffffffu, rs0, 2);
        rs1 += __shfl_xor_sync(0xffffffffu, rs1, 1);
        rs1 += __shfl_xor_sync(0xffffffffu, rs1, 2);
        l0 = l0 * a0 + rs0;
        l1 = l1 * a1 + rs1;
        #pragma unroll
        for (int nt = 0; nt < 8; nt++) {
            o[nt][0] *= a0; o[nt][1] *= a0;
            o[nt][2] *= a1; o[nt][3] *= a1;
        }

        // ---- O += P V (3-term split).
        #pragma unroll
        for (int kt = 0; kt < 4; kt++) {
            uint32_t ph[4], pl[4];
            tsplit2(s[2 * kt][0],     s[2 * kt][1],     ph[0], pl[0]);
            tsplit2(s[2 * kt][2],     s[2 * kt][3],     ph[1], pl[1]);
            tsplit2(s[2 * kt + 1][0], s[2 * kt + 1][1], ph[2], pl[2]);
            tsplit2(s[2 * kt + 1][2], s[2 * kt + 1][3], ph[3], pl[3]);
            #pragma unroll
            for (int nt = 0; nt < 8; nt++) {
                int cb = (nt * 8 + grow) * KPITCH + kt * 16 + tg * 2;
                uint32_t bh0 = lds32(Vth + cb), bh1 = lds32(Vth + cb + 8);
                uint32_t bl0 = lds32(Vtl + cb), bl1 = lds32(Vtl + cb + 8);
                mma_bf16(o[nt], ph[0], ph[1], ph[2], ph[3], bh0, bh1);
                mma_bf16(o[nt], ph[0], ph[1], ph[2], ph[3], bl0, bl1);
                mma_bf16(o[nt], pl[0], pl[1], pl[2], pl[3], bh0, bh1);
            }
        }
    }

    float inv0 = 1.0f / l0, inv1 = 1.0f / l1;
    float* Og = Out + (size_t)(b * SS + qb * 64 + wm * 16) * HH;
    #pragma unroll
    for (int nt = 0; nt < 8; nt++) {
        *(float2*)(Og + grow * HH + nt * 8 + tg * 2) =
            make_float2(o[nt][0] * inv0, o[nt][1] * inv0);
        *(float2*)(Og + (grow + 8) * HH + nt * 8 + tg * 2) =
            make_float2(o[nt][2] * inv1, o[nt][3] * inv1);
    }
}

// ---------------------------------------------------------------------------
extern "C" void kernel_launch(void* const* d_in, const int* in_sizes, int n_in,
                              void* d_out, int out_size)
{
    const float* x  = (const float*)d_in[0];
    const float* Wq = (const float*)d_in[1];
    const float* Wk = (const float*)d_in[2];
    const float* Wv = (const float*)d_in[3];
    float* out = (float*)d_out;
    (void)in_sizes; (void)n_in; (void)out_size;

    cudaFuncSetAttribute(attn_mma, cudaFuncAttributeMaxDynamicSharedMemorySize,
                         ATTN_SMEM);

    prep_w<<<768, 256>>>(Wq, Wk, Wv);
    qkv_mma<<<(BB * SS) / 64, 256>>>(x);
    prep_vt<<<dim3(SS / 64, BB), 256>>>();
    attn_mma<<<dim3(SS / 64, BB), 128, ATTN_SMEM>>>(out);
}

// round 9
// speedup vs baseline: 1.1340x; 1.1340x over previous
#include <cuda_runtime.h>
#include <cuda_bf16.h>
#include <math.h>
#include <stdint.h>

#define BB 8
#define SS 2048
#define DD 1024
#define HH 64

// Scratch.
__device__ float g_Q[BB * SS * HH];                 // fp32 Q
__device__ float g_V[BB * SS * HH];                 // fp32 V (input to prep_vt)
__device__ uint32_t g_Khp[BB * SS * 32];            // K hi, bf16x2 pairs along h
__device__ uint32_t g_Klp[BB * SS * 32];            // K lo
__device__ uint32_t g_Vthp[BB * 64 * 1024];         // V^T hi: [b][h][s/2] pairs along s
__device__ uint32_t g_Vtlp[BB * 64 * 1024];         // V^T lo
__device__ __nv_bfloat16 g_Bh[192 * 1024];          // weights hi  [n][k]
__device__ __nv_bfloat16 g_Bl[192 * 1024];          // weights lo

// ---------------------------------------------------------------------------
// Truncation-based fp32 -> bf16 hi/lo split for a pair of floats.
// ---------------------------------------------------------------------------
__device__ __forceinline__ void tsplit2(float a, float b, uint32_t& hi, uint32_t& lo) {
    uint32_t ia = __float_as_uint(a), ib = __float_as_uint(b);
    hi = __byte_perm(ia, ib, 0x7632);
    float ra = a - __uint_as_float(ia & 0xFFFF0000u);
    float rb = b - __uint_as_float(ib & 0xFFFF0000u);
    asm("cvt.rn.bf16x2.f32 %0, %1, %2;" : "=r"(lo) : "f"(rb), "f"(ra));
}

// Fast exp2 for x <= 0 (clamped at -80): FMA/ALU pipes only, no MUFU.
__device__ __forceinline__ float exp2_fast(float x) {
    x = fmaxf(x, -80.0f);
    float z = x + 12582912.0f;
    float n = z - 12582912.0f;
    float f = x - n;
    float p =            1.3333558e-3f;
    p = fmaf(p, f, 9.6181291e-3f);
    p = fmaf(p, f, 5.5504109e-2f);
    p = fmaf(p, f, 2.4022650e-1f);
    p = fmaf(p, f, 6.9314718e-1f);
    p = fmaf(p, f, 1.0f);
    int e = __float_as_int(z);
    float sc = __int_as_float((e + (127 - 0x4B400000)) << 23);
    return p * sc;
}

__device__ __forceinline__ void mma_bf16(float c[4],
                                         uint32_t a0, uint32_t a1, uint32_t a2, uint32_t a3,
                                         uint32_t b0, uint32_t b1) {
    asm volatile(
        "mma.sync.aligned.m16n8k16.row.col.f32.bf16.bf16.f32 "
        "{%0,%1,%2,%3}, {%4,%5,%6,%7}, {%8,%9}, {%0,%1,%2,%3};"
        : "+f"(c[0]), "+f"(c[1]), "+f"(c[2]), "+f"(c[3])
        : "r"(a0), "r"(a1), "r"(a2), "r"(a3), "r"(b0), "r"(b1));
}

__device__ __forceinline__ uint32_t lds32(const __nv_bfloat16* p) {
    return *(const uint32_t*)p;
}

// ---------------------------------------------------------------------------
// Kernel 0: split weights W[k][n] fp32 -> g_Bh/g_Bl[n_global][k] bf16.
// ---------------------------------------------------------------------------
__global__ void prep_w(const float* __restrict__ Wq,
                       const float* __restrict__ Wk,
                       const float* __restrict__ Wv)
{
    int i = blockIdx.x * blockDim.x + threadIdx.x;
    int n = i >> 10;
    int k = i & 1023;
    int m = n >> 6;
    int col = n & 63;
    const float* W = (m == 0) ? Wq : (m == 1) ? Wk : Wv;
    float w = W[k * 64 + col];
    __nv_bfloat16 h = __float2bfloat16(w);
    float lo = w - __bfloat162float(h);
    g_Bh[(size_t)n * 1024 + k] = h;
    g_Bl[(size_t)n * 1024 + k] = __float2bfloat16(lo);
}

// ---------------------------------------------------------------------------
// Kernel 1: QKV projection (R7 version, M=128). 256 threads,
// warp grid 4(M) x 2(N): warp tile 32 x 96 = 2 m-tiles x 12 n-tiles.
// ---------------------------------------------------------------------------
#define APITCH 36
#define BPITCH 36

__global__ __launch_bounds__(256) void qkv_mma(const float* __restrict__ x)
{
    __shared__ __align__(16) __nv_bfloat16 Ah[128 * APITCH];
    __shared__ __align__(16) __nv_bfloat16 Al[128 * APITCH];
    __shared__ __align__(16) __nv_bfloat16 Bh[192 * BPITCH];
    __shared__ __align__(16) __nv_bfloat16 Bl[192 * BPITCH];

    const int tid = threadIdx.x;
    const int wid = tid >> 5;
    const int lane = tid & 31;
    const int grow = lane >> 2;
    const int tg = lane & 3;
    const int warp_m = wid & 3;
    const int warp_n = wid >> 2;
    const int row0 = blockIdx.x * 128;

    float acc[2][12][4] = {};

    for (int k0 = 0; k0 < DD; k0 += 32) {
        #pragma unroll
        for (int i = 0; i < 4; i++) {
            int idx = tid + (i << 8);
            int r = idx >> 3;
            int c4 = idx & 7;
            float4 f = *(const float4*)(x + (size_t)(row0 + r) * DD + k0 + c4 * 4);
            uint32_t h01, l01, h23, l23;
            tsplit2(f.x, f.y, h01, l01);
            tsplit2(f.z, f.w, h23, l23);
            int off = r * APITCH + c4 * 4;
            *(uint2*)&Ah[off] = make_uint2(h01, h23);
            *(uint2*)&Al[off] = make_uint2(l01, l23);
        }
        #pragma unroll
        for (int i = 0; i < 3; i++) {
            int idx = tid + (i << 8);
            int r = idx >> 2;
            int q = idx & 3;
            int off = r * BPITCH + q * 8;
            uint4 vh = *(const uint4*)(g_Bh + (size_t)r * 1024 + k0 + q * 8);
            uint4 vl = *(const uint4*)(g_Bl + (size_t)r * 1024 + k0 + q * 8);
            *(uint2*)&Bh[off]     = make_uint2(vh.x, vh.y);
            *(uint2*)&Bh[off + 4] = make_uint2(vh.z, vh.w);
            *(uint2*)&Bl[off]     = make_uint2(vl.x, vl.y);
            *(uint2*)&Bl[off + 4] = make_uint2(vl.z, vl.w);
        }
        __syncthreads();

        #pragma unroll
        for (int ks = 0; ks < 2; ks++) {
            const int kofs = ks * 16 + tg * 2;
            uint32_t ah[2][4], al[2][4];
            #pragma unroll
            for (int mt = 0; mt < 2; mt++) {
                int rb = (warp_m * 32 + mt * 16 + grow) * APITCH + kofs;
                ah[mt][0] = lds32(Ah + rb);
                ah[mt][1] = lds32(Ah + rb + 8 * APITCH);
                ah[mt][2] = lds32(Ah + rb + 8);
                ah[mt][3] = lds32(Ah + rb + 8 * APITCH + 8);
                al[mt][0] = lds32(Al + rb);
                al[mt][1] = lds32(Al + rb + 8 * APITCH);
                al[mt][2] = lds32(Al + rb + 8);
                al[mt][3] = lds32(Al + rb + 8 * APITCH + 8);
            }
            #pragma unroll
            for (int nt = 0; nt < 12; nt++) {
                int cb = (warp_n * 96 + nt * 8 + grow) * BPITCH + kofs;
                uint32_t bh0 = lds32(Bh + cb);
                uint32_t bh1 = lds32(Bh + cb + 8);
                uint32_t bl0 = lds32(Bl + cb);
                uint32_t bl1 = lds32(Bl + cb + 8);
                #pragma unroll
                for (int mt = 0; mt < 2; mt++) {
                    mma_bf16(acc[mt][nt], ah[mt][0], ah[mt][1], ah[mt][2], ah[mt][3], bh0, bh1);
                    mma_bf16(acc[mt][nt], ah[mt][0], ah[mt][1], ah[mt][2], ah[mt][3], bl0, bl1);
                    mma_bf16(acc[mt][nt], al[mt][0], al[mt][1], al[mt][2], al[mt][3], bh0, bh1);
                }
            }
        }
        __syncthreads();
    }

    #pragma unroll
    for (int mt = 0; mt < 2; mt++) {
        int r = row0 + warp_m * 32 + mt * 16 + grow;
        #pragma unroll
        for (int nt = 0; nt < 12; nt++) {
            int col = warp_n * 96 + nt * 8 + tg * 2;
            int mat = col >> 6;
            int c = col & 63;
            if (mat == 1) {
                uint32_t h0, l0, h1, l1;
                tsplit2(acc[mt][nt][0], acc[mt][nt][1], h0, l0);
                tsplit2(acc[mt][nt][2], acc[mt][nt][3], h1, l1);
                int pidx = c >> 1;
                g_Khp[(size_t)r * 32 + pidx] = h0;
                g_Klp[(size_t)r * 32 + pidx] = l0;
                g_Khp[(size_t)(r + 8) * 32 + pidx] = h1;
                g_Klp[(size_t)(r + 8) * 32 + pidx] = l1;
            } else {
                float* dst = (mat == 0) ? g_Q : g_V;
                *(float2*)(dst + (size_t)r * 64 + c) =
                    make_float2(acc[mt][nt][0], acc[mt][nt][1]);
                *(float2*)(dst + (size_t)(r + 8) * 64 + c) =
                    make_float2(acc[mt][nt][2], acc[mt][nt][3]);
            }
        }
    }
}

// ---------------------------------------------------------------------------
// Kernel 1b: transpose + split V once.
// ---------------------------------------------------------------------------
__global__ __launch_bounds__(256) void prep_vt()
{
    __shared__ float vt[64 * 65];
    const int tid = threadIdx.x;
    const int s0 = blockIdx.x * 64;
    const int b  = blockIdx.y;

    #pragma unroll
    for (int i = 0; i < 4; i++) {
        int idx = tid + (i << 8);
        int r = idx >> 4;
        int c4 = (idx & 15) << 2;
        float4 f = *(const float4*)(g_V + (size_t)(b * SS + s0 + r) * 64 + c4);
        vt[r * 65 + c4 + 0] = f.x;  vt[r * 65 + c4 + 1] = f.y;
        vt[r * 65 + c4 + 2] = f.z;  vt[r * 65 + c4 + 3] = f.w;
    }
    __syncthreads();

    #pragma unroll
    for (int i = 0; i < 8; i++) {
        int idx = tid + (i << 8);
        int h  = idx >> 5;
        int sp = idx & 31;
        float v0 = vt[(sp * 2 + 0) * 65 + h];
        float v1 = vt[(sp * 2 + 1) * 65 + h];
        uint32_t hi, lo;
        tsplit2(v0, v1, hi, lo);
        size_t o = (size_t)(b * 64 + h) * 1024 + (s0 >> 1) + sp;
        g_Vthp[o] = hi;
        g_Vtlp[o] = lo;
    }
}

// ---------------------------------------------------------------------------
// Kernel 2: causal flash attention, Q-tile 128 rows, 256 threads (8 warps).
// Warp wm handles q-rows [qb*128 + wm*16, +16). K/V tiles = 64 keys, reused
// across all 8 warps (2x amortization vs 64-row tiles). Static smem 36KB.
// Fully-masked tiles skipped per-warp.
// ---------------------------------------------------------------------------
#define KPITCH 72
#define SCL 0.18033688011112042f   /* 0.125 * log2(e) */

__global__ __launch_bounds__(256) void attn_mma(float* __restrict__ Out)
{
    __shared__ __align__(16) __nv_bfloat16 Kh[64 * KPITCH];
    __shared__ __align__(16) __nv_bfloat16 Kl[64 * KPITCH];
    __shared__ __align__(16) __nv_bfloat16 Vth[64 * KPITCH];
    __shared__ __align__(16) __nv_bfloat16 Vtl[64 * KPITCH];

    const int tid = threadIdx.x;
    const int wm = tid >> 5;            // 0..7 -> 16 q-rows each
    const int lane = tid & 31;
    const int grow = lane >> 2;
    const int tg = lane & 3;
    const int qb = blockIdx.x;          // 128-row q block (0..15)
    const int b  = blockIdx.y;

    const float* Qg = g_Q + (size_t)(b * SS + qb * 128 + wm * 16) * HH;

    // Hoist Q fragments (hi/lo) into registers.
    uint32_t qh[4][4], ql[4][4];
    #pragma unroll
    for (int kt = 0; kt < 4; kt++) {
        float2 v00 = *(const float2*)(Qg + grow * HH + kt * 16 + tg * 2);
        float2 v10 = *(const float2*)(Qg + (grow + 8) * HH + kt * 16 + tg * 2);
        float2 v01 = *(const float2*)(Qg + grow * HH + kt * 16 + tg * 2 + 8);
        float2 v11 = *(const float2*)(Qg + (grow + 8) * HH + kt * 16 + tg * 2 + 8);
        tsplit2(v00.x, v00.y, qh[kt][0], ql[kt][0]);
        tsplit2(v10.x, v10.y, qh[kt][1], ql[kt][1]);
        tsplit2(v01.x, v01.y, qh[kt][2], ql[kt][2]);
        tsplit2(v11.x, v11.y, qh[kt][3], ql[kt][3]);
    }

    float o[8][4] = {};
    float m0 = -1e30f, m1 = -1e30f, l0 = 0.0f, l1 = 0.0f;
    const int warp_row0 = qb * 128 + wm * 16;       // warp's lowest q-row
    const int qr0 = warp_row0 + grow;               // thread's base q-row

    const uint4* Khg4 = (const uint4*)(g_Khp + (size_t)b * SS * 32);
    const uint4* Klg4 = (const uint4*)(g_Klp + (size_t)b * SS * 32);
    const uint4* Vhg4 = (const uint4*)(g_Vthp + (size_t)b * 64 * 1024);
    const uint4* Vlg4 = (const uint4*)(g_Vtlp + (size_t)b * 64 * 1024);

    const int kbmax = 2 * qb + 1;       // key tiles covering [0, (qb+1)*128)

    for (int kb = 0; kb <= kbmax; kb++) {
        // ---- fill K/V tiles: 256 threads x 2 uint4 per array.
        #pragma unroll
        for (int i = 0; i < 2; i++) {
            int idx = tid + (i << 8);   // 0..511
            int r = idx >> 3, q = idx & 7;
            // K rows: global key row kb*64 + r, 8 uint4 per row.
            *(uint4*)&Kh[r * KPITCH + q * 8] = Khg4[(size_t)(kb * 64 + r) * 8 + q];
            *(uint4*)&Kl[r * KPITCH + q * 8] = Klg4[(size_t)(kb * 64 + r) * 8 + q];
            // V^T rows: h = r, 256 uint4 per h-row, tile offset kb*8.
            *(uint4*)&Vth[r * KPITCH + q * 8] = Vhg4[(size_t)r * 256 + kb * 8 + q];
            *(uint4*)&Vtl[r * KPITCH + q * 8] = Vlg4[(size_t)r * 256 + kb * 8 + q];
        }
        __syncthreads();

        // Skip tiles fully above this warp's diagonal (all keys > all rows).
        if (kb * 64 <= warp_row0 + 15) {
            // ---- S = Q K^T (3-term split).
            float s[8][4] = {};
            #pragma unroll
            for (int nt = 0; nt < 8; nt++) {
                #pragma unroll
                for (int kt = 0; kt < 4; kt++) {
                    int cb = (nt * 8 + grow) * KPITCH + kt * 16 + tg * 2;
                    uint32_t bh0 = lds32(Kh + cb), bh1 = lds32(Kh + cb + 8);
                    uint32_t bl0 = lds32(Kl + cb), bl1 = lds32(Kl + cb + 8);
                    mma_bf16(s[nt], qh[kt][0], qh[kt][1], qh[kt][2], qh[kt][3], bh0, bh1);
                    mma_bf16(s[nt], qh[kt][0], qh[kt][1], qh[kt][2], qh[kt][3], bl0, bl1);
                    mma_bf16(s[nt], ql[kt][0], ql[kt][1], ql[kt][2], ql[kt][3], bh0, bh1);
                }
            }

            // ---- scale + causal mask (only tiles overlapping the diagonal).
            if (kb * 64 + 63 > qr0) {
                #pragma unroll
                for (int nt = 0; nt < 8; nt++) {
                    int kc = kb * 64 + nt * 8 + tg * 2;
                    s[nt][0] = (kc     > qr0)     ? -1e30f : s[nt][0] * SCL;
                    s[nt][1] = (kc + 1 > qr0)     ? -1e30f : s[nt][1] * SCL;
                    s[nt][2] = (kc     > qr0 + 8) ? -1e30f : s[nt][2] * SCL;
                    s[nt][3] = (kc + 1 > qr0 + 8) ? -1e30f : s[nt][3] * SCL;
                }
            } else {
                #pragma unroll
                for (int nt = 0; nt < 8; nt++) {
                    s[nt][0] *= SCL; s[nt][1] *= SCL;
                    s[nt][2] *= SCL; s[nt][3] *= SCL;
                }
            }

            // ---- online softmax (base-2).
            float mx0 = -1e30f, mx1 = -1e30f;
            #pragma unroll
            for (int nt = 0; nt < 8; nt++) {
                mx0 = fmaxf(mx0, fmaxf(s[nt][0], s[nt][1]));
                mx1 = fmaxf(mx1, fmaxf(s[nt][2], s[nt][3]));
            }
            mx0 = fmaxf(mx0, __shfl_xor_sync(0xffffffffu, mx0, 1));
            mx0 = fmaxf(mx0, __shfl_xor_sync(0xffffffffu, mx0, 2));
            mx1 = fmaxf(mx1, __shfl_xor_sync(0xffffffffu, mx1, 1));
            mx1 = fmaxf(mx1, __shfl_xor_sync(0xffffffffu, mx1, 2));
            float nm0 = fmaxf(m0, mx0), nm1 = fmaxf(m1, mx1);
            float a0 = exp2_fast(m0 - nm0), a1 = exp2_fast(m1 - nm1);
            m0 = nm0; m1 = nm1;

            float rs0 = 0.0f, rs1 = 0.0f;
            #pragma unroll
            for (int nt = 0; nt < 8; nt++) {
                float p0 = exp2_fast(s[nt][0] - nm0);
                float p1 = exp2_fast(s[nt][1] - nm0);
                float p2 = exp2_fast(s[nt][2] - nm1);
                float p3 = exp2_fast(s[nt][3] - nm1);
                s[nt][0] = p0; s[nt][1] = p1; s[nt][2] = p2; s[nt][3] = p3;
                rs0 += p0 + p1;
                rs1 += p2 + p3;
            }
            rs0 += __shfl_xor_sync(0xffffffffu, rs0, 1);
            rs0 += __shfl_xor_sync(0xffffffffu, rs0, 2);
            rs1 += __shfl_xor_sync(0xffffffffu, rs1, 1);
            rs1 += __shfl_xor_sync(0xffffffffu, rs1, 2);
            l0 = l0 * a0 + rs0;
            l1 = l1 * a1 + rs1;
            #pragma unroll
            for (int nt = 0; nt < 8; nt++) {
                o[nt][0] *= a0; o[nt][1] *= a0;
                o[nt][2] *= a1; o[nt][3] *= a1;
            }

            // ---- O += P V (3-term split).
            #pragma unroll
            for (int kt = 0; kt < 4; kt++) {
                uint32_t ph[4], pl[4];
                tsplit2(s[2 * kt][0],     s[2 * kt][1],     ph[0], pl[0]);
                tsplit2(s[2 * kt][2],     s[2 * kt][3],     ph[1], pl[1]);
                tsplit2(s[2 * kt + 1][0], s[2 * kt + 1][1], ph[2], pl[2]);
                tsplit2(s[2 * kt + 1][2], s[2 * kt + 1][3], ph[3], pl[3]);
                #pragma unroll
                for (int nt = 0; nt < 8; nt++) {
                    int cb = (nt * 8 + grow) * KPITCH + kt * 16 + tg * 2;
                    uint32_t bh0 = lds32(Vth + cb), bh1 = lds32(Vth + cb + 8);
                    uint32_t bl0 = lds32(Vtl + cb), bl1 = lds32(Vtl + cb + 8);
                    mma_bf16(o[nt], ph[0], ph[1], ph[2], ph[3], bh0, bh1);
                    mma_bf16(o[nt], ph[0], ph[1], ph[2], ph[3], bl0, bl1);
                    mma_bf16(o[nt], pl[0], pl[1], pl[2], pl[3], bh0, bh1);
                }
            }
        }
        __syncthreads();
    }

    float inv0 = 1.0f / l0, inv1 = 1.0f / l1;
    float* Og = Out + (size_t)(b * SS + qb * 128 + wm * 16) * HH;
    #pragma unroll
    for (int nt = 0; nt < 8; nt++) {
        *(float2*)(Og + grow * HH + nt * 8 + tg * 2) =
            make_float2(o[nt][0] * inv0, o[nt][1] * inv0);
        *(float2*)(Og + (grow + 8) * HH + nt * 8 + tg * 2) =
            make_float2(o[nt][2] * inv1, o[nt][3] * inv1);
    }
}

// ---------------------------------------------------------------------------
extern "C" void kernel_launch(void* const* d_in, const int* in_sizes, int n_in,
                              void* d_out, int out_size)
{
    const float* x  = (const float*)d_in[0];
    const float* Wq = (const float*)d_in[1];
    const float* Wk = (const float*)d_in[2];
    const float* Wv = (const float*)d_in[3];
    float* out = (float*)d_out;
    (void)in_sizes; (void)n_in; (void)out_size;

    prep_w<<<768, 256>>>(Wq, Wk, Wv);
    qkv_mma<<<(BB * SS) / 128, 256>>>(x);
    prep_vt<<<dim3(SS / 64, BB), 256>>>();
    attn_mma<<<dim3(SS / 128, BB), 256>>>(out);
}

// round 10
// speedup vs baseline: 1.3835x; 1.2201x over previous
#include <cuda_runtime.h>
#include <cuda_bf16.h>
#include <math.h>
#include <stdint.h>

#define BB 8
#define SS 2048
#define DD 1024
#define HH 64

// Scratch.
__device__ float g_Q[BB * SS * HH];                 // fp32 Q
__device__ float g_V[BB * SS * HH];                 // fp32 V (input to prep_vt)
__device__ uint32_t g_Khp[BB * SS * 32];            // K hi, bf16x2 pairs along h
__device__ uint32_t g_Klp[BB * SS * 32];            // K lo
__device__ uint32_t g_Vthp[BB * 64 * 1024];         // V^T hi: [b][h][s/2] pairs along s
__device__ uint32_t g_Vtlp[BB * 64 * 1024];         // V^T lo
__device__ __nv_bfloat16 g_Bh[192 * 1024];          // weights hi  [n][k]
__device__ __nv_bfloat16 g_Bl[192 * 1024];          // weights lo

// Split-K partials: unit = (b, qb, ci) -> 64x64 unnormalized O + per-row m,l.
__device__ float g_pO[BB * 32 * 4 * 64 * 64];       // 16.8 MB
__device__ float g_pm[BB * 32 * 4 * 64];
__device__ float g_pl[BB * 32 * 4 * 64];

// ---------------------------------------------------------------------------
__device__ __forceinline__ void tsplit2(float a, float b, uint32_t& hi, uint32_t& lo) {
    uint32_t ia = __float_as_uint(a), ib = __float_as_uint(b);
    hi = __byte_perm(ia, ib, 0x7632);
    float ra = a - __uint_as_float(ia & 0xFFFF0000u);
    float rb = b - __uint_as_float(ib & 0xFFFF0000u);
    asm("cvt.rn.bf16x2.f32 %0, %1, %2;" : "=r"(lo) : "f"(rb), "f"(ra));
}

__device__ __forceinline__ float exp2_fast(float x) {
    x = fmaxf(x, -80.0f);
    float z = x + 12582912.0f;
    float n = z - 12582912.0f;
    float f = x - n;
    float p =            1.3333558e-3f;
    p = fmaf(p, f, 9.6181291e-3f);
    p = fmaf(p, f, 5.5504109e-2f);
    p = fmaf(p, f, 2.4022650e-1f);
    p = fmaf(p, f, 6.9314718e-1f);
    p = fmaf(p, f, 1.0f);
    int e = __float_as_int(z);
    float sc = __int_as_float((e + (127 - 0x4B400000)) << 23);
    return p * sc;
}

__device__ __forceinline__ void mma_bf16(float c[4],
                                         uint32_t a0, uint32_t a1, uint32_t a2, uint32_t a3,
                                         uint32_t b0, uint32_t b1) {
    asm volatile(
        "mma.sync.aligned.m16n8k16.row.col.f32.bf16.bf16.f32 "
        "{%0,%1,%2,%3}, {%4,%5,%6,%7}, {%8,%9}, {%0,%1,%2,%3};"
        : "+f"(c[0]), "+f"(c[1]), "+f"(c[2]), "+f"(c[3])
        : "r"(a0), "r"(a1), "r"(a2), "r"(a3), "r"(b0), "r"(b1));
}

__device__ __forceinline__ uint32_t lds32(const __nv_bfloat16* p) {
    return *(const uint32_t*)p;
}

// ---------------------------------------------------------------------------
// Kernel 0: split weights.
// ---------------------------------------------------------------------------
__global__ void prep_w(const float* __restrict__ Wq,
                       const float* __restrict__ Wk,
                       const float* __restrict__ Wv)
{
    int i = blockIdx.x * blockDim.x + threadIdx.x;
    int n = i >> 10;
    int k = i & 1023;
    int m = n >> 6;
    int col = n & 63;
    const float* W = (m == 0) ? Wq : (m == 1) ? Wk : Wv;
    float w = W[k * 64 + col];
    __nv_bfloat16 h = __float2bfloat16(w);
    float lo = w - __bfloat162float(h);
    g_Bh[(size_t)n * 1024 + k] = h;
    g_Bl[(size_t)n * 1024 + k] = __float2bfloat16(lo);
}

// ---------------------------------------------------------------------------
// Kernel 1: QKV projection (unchanged R7/R9 version, M=128).
// ---------------------------------------------------------------------------
#define APITCH 36
#define BPITCH 36

__global__ __launch_bounds__(256) void qkv_mma(const float* __restrict__ x)
{
    __shared__ __align__(16) __nv_bfloat16 Ah[128 * APITCH];
    __shared__ __align__(16) __nv_bfloat16 Al[128 * APITCH];
    __shared__ __align__(16) __nv_bfloat16 Bh[192 * BPITCH];
    __shared__ __align__(16) __nv_bfloat16 Bl[192 * BPITCH];

    const int tid = threadIdx.x;
    const int wid = tid >> 5;
    const int lane = tid & 31;
    const int grow = lane >> 2;
    const int tg = lane & 3;
    const int warp_m = wid & 3;
    const int warp_n = wid >> 2;
    const int row0 = blockIdx.x * 128;

    float acc[2][12][4] = {};

    for (int k0 = 0; k0 < DD; k0 += 32) {
        #pragma unroll
        for (int i = 0; i < 4; i++) {
            int idx = tid + (i << 8);
            int r = idx >> 3;
            int c4 = idx & 7;
            float4 f = *(const float4*)(x + (size_t)(row0 + r) * DD + k0 + c4 * 4);
            uint32_t h01, l01, h23, l23;
            tsplit2(f.x, f.y, h01, l01);
            tsplit2(f.z, f.w, h23, l23);
            int off = r * APITCH + c4 * 4;
            *(uint2*)&Ah[off] = make_uint2(h01, h23);
            *(uint2*)&Al[off] = make_uint2(l01, l23);
        }
        #pragma unroll
        for (int i = 0; i < 3; i++) {
            int idx = tid + (i << 8);
            int r = idx >> 2;
            int q = idx & 3;
            int off = r * BPITCH + q * 8;
            uint4 vh = *(const uint4*)(g_Bh + (size_t)r * 1024 + k0 + q * 8);
            uint4 vl = *(const uint4*)(g_Bl + (size_t)r * 1024 + k0 + q * 8);
            *(uint2*)&Bh[off]     = make_uint2(vh.x, vh.y);
            *(uint2*)&Bh[off + 4] = make_uint2(vh.z, vh.w);
            *(uint2*)&Bl[off]     = make_uint2(vl.x, vl.y);
            *(uint2*)&Bl[off + 4] = make_uint2(vl.z, vl.w);
        }
        __syncthreads();

        #pragma unroll
        for (int ks = 0; ks < 2; ks++) {
            const int kofs = ks * 16 + tg * 2;
            uint32_t ah[2][4], al[2][4];
            #pragma unroll
            for (int mt = 0; mt < 2; mt++) {
                int rb = (warp_m * 32 + mt * 16 + grow) * APITCH + kofs;
                ah[mt][0] = lds32(Ah + rb);
                ah[mt][1] = lds32(Ah + rb + 8 * APITCH);
                ah[mt][2] = lds32(Ah + rb + 8);
                ah[mt][3] = lds32(Ah + rb + 8 * APITCH + 8);
                al[mt][0] = lds32(Al + rb);
                al[mt][1] = lds32(Al + rb + 8 * APITCH);
                al[mt][2] = lds32(Al + rb + 8);
                al[mt][3] = lds32(Al + rb + 8 * APITCH + 8);
            }
            #pragma unroll
            for (int nt = 0; nt < 12; nt++) {
                int cb = (warp_n * 96 + nt * 8 + grow) * BPITCH + kofs;
                uint32_t bh0 = lds32(Bh + cb);
                uint32_t bh1 = lds32(Bh + cb + 8);
                uint32_t bl0 = lds32(Bl + cb);
                uint32_t bl1 = lds32(Bl + cb + 8);
                #pragma unroll
                for (int mt = 0; mt < 2; mt++) {
                    mma_bf16(acc[mt][nt], ah[mt][0], ah[mt][1], ah[mt][2], ah[mt][3], bh0, bh1);
                    mma_bf16(acc[mt][nt], ah[mt][0], ah[mt][1], ah[mt][2], ah[mt][3], bl0, bl1);
                    mma_bf16(acc[mt][nt], al[mt][0], al[mt][1], al[mt][2], al[mt][3], bh0, bh1);
                }
            }
        }
        __syncthreads();
    }

    #pragma unroll
    for (int mt = 0; mt < 2; mt++) {
        int r = row0 + warp_m * 32 + mt * 16 + grow;
        #pragma unroll
        for (int nt = 0; nt < 12; nt++) {
            int col = warp_n * 96 + nt * 8 + tg * 2;
            int mat = col >> 6;
            int c = col & 63;
            if (mat == 1) {
                uint32_t h0, l0, h1, l1;
                tsplit2(acc[mt][nt][0], acc[mt][nt][1], h0, l0);
                tsplit2(acc[mt][nt][2], acc[mt][nt][3], h1, l1);
                int pidx = c >> 1;
                g_Khp[(size_t)r * 32 + pidx] = h0;
                g_Klp[(size_t)r * 32 + pidx] = l0;
                g_Khp[(size_t)(r + 8) * 32 + pidx] = h1;
                g_Klp[(size_t)(r + 8) * 32 + pidx] = l1;
            } else {
                float* dst = (mat == 0) ? g_Q : g_V;
                *(float2*)(dst + (size_t)r * 64 + c) =
                    make_float2(acc[mt][nt][0], acc[mt][nt][1]);
                *(float2*)(dst + (size_t)(r + 8) * 64 + c) =
                    make_float2(acc[mt][nt][2], acc[mt][nt][3]);
            }
        }
    }
}

// ---------------------------------------------------------------------------
// Kernel 1b: transpose + split V once.
// ---------------------------------------------------------------------------
__global__ __launch_bounds__(256) void prep_vt()
{
    __shared__ float vt[64 * 65];
    const int tid = threadIdx.x;
    const int s0 = blockIdx.x * 64;
    const int b  = blockIdx.y;

    #pragma unroll
    for (int i = 0; i < 4; i++) {
        int idx = tid + (i << 8);
        int r = idx >> 4;
        int c4 = (idx & 15) << 2;
        float4 f = *(const float4*)(g_V + (size_t)(b * SS + s0 + r) * 64 + c4);
        vt[r * 65 + c4 + 0] = f.x;  vt[r * 65 + c4 + 1] = f.y;
        vt[r * 65 + c4 + 2] = f.z;  vt[r * 65 + c4 + 3] = f.w;
    }
    __syncthreads();

    #pragma unroll
    for (int i = 0; i < 8; i++) {
        int idx = tid + (i << 8);
        int h  = idx >> 5;
        int sp = idx & 31;
        float v0 = vt[(sp * 2 + 0) * 65 + h];
        float v1 = vt[(sp * 2 + 1) * 65 + h];
        uint32_t hi, lo;
        tsplit2(v0, v1, hi, lo);
        size_t o = (size_t)(b * 64 + h) * 1024 + (s0 >> 1) + sp;
        g_Vthp[o] = hi;
        g_Vtlp[o] = lo;
    }
}

// ---------------------------------------------------------------------------
// Kernel 2a: split-K flash attention partials.
// Unit u (0..79) per batch -> (qb, ci): chunk ci covers k-tiles
// [ci*8, min(ci*8+7, qb)]. nc(qb) = (qb>>3)+1.  640 CTAs, <=8 iters each.
// 4 warps, 64 q-rows, unnormalized partial O + per-row (m, l) in base-2.
// ---------------------------------------------------------------------------
#define KPITCH 72
#define SCL 0.18033688011112042f   /* 0.125 * log2(e) */

__global__ __launch_bounds__(128) void attn_part(float* __restrict__ dummy)
{
    __shared__ __align__(16) __nv_bfloat16 Kh[64 * KPITCH];
    __shared__ __align__(16) __nv_bfloat16 Kl[64 * KPITCH];
    __shared__ __align__(16) __nv_bfloat16 Vth[64 * KPITCH];
    __shared__ __align__(16) __nv_bfloat16 Vtl[64 * KPITCH];
    (void)dummy;

    const int tid = threadIdx.x;
    const int wm = tid >> 5;
    const int lane = tid & 31;
    const int grow = lane >> 2;
    const int tg = lane & 3;
    const int u = blockIdx.x;          // 0..79
    const int b = blockIdx.y;

    int qb, ci;
    if (u < 8)       { qb = u;                 ci = 0; }
    else if (u < 24) { qb = 8  + ((u - 8) >> 1);  ci = (u - 8) & 1; }
    else if (u < 48) { qb = 16 + (u - 24) / 3;    ci = (u - 24) % 3; }
    else             { qb = 24 + ((u - 48) >> 2); ci = (u - 48) & 3; }

    const int kb0 = ci * 8;
    const int kb1 = min(kb0 + 7, qb);

    const float* Qg = g_Q + (size_t)(b * SS + qb * 64 + wm * 16) * HH;

    uint32_t qh[4][4], ql[4][4];
    #pragma unroll
    for (int kt = 0; kt < 4; kt++) {
        float2 v00 = *(const float2*)(Qg + grow * HH + kt * 16 + tg * 2);
        float2 v10 = *(const float2*)(Qg + (grow + 8) * HH + kt * 16 + tg * 2);
        float2 v01 = *(const float2*)(Qg + grow * HH + kt * 16 + tg * 2 + 8);
        float2 v11 = *(const float2*)(Qg + (grow + 8) * HH + kt * 16 + tg * 2 + 8);
        tsplit2(v00.x, v00.y, qh[kt][0], ql[kt][0]);
        tsplit2(v10.x, v10.y, qh[kt][1], ql[kt][1]);
        tsplit2(v01.x, v01.y, qh[kt][2], ql[kt][2]);
        tsplit2(v11.x, v11.y, qh[kt][3], ql[kt][3]);
    }

    float o[8][4] = {};
    float m0 = -1e30f, m1 = -1e30f, l0 = 0.0f, l1 = 0.0f;
    const int qr0 = qb * 64 + wm * 16 + grow;

    const uint4* Khg4 = (const uint4*)(g_Khp + (size_t)b * SS * 32);
    const uint4* Klg4 = (const uint4*)(g_Klp + (size_t)b * SS * 32);
    const uint4* Vhg4 = (const uint4*)(g_Vthp + (size_t)b * 64 * 1024);
    const uint4* Vlg4 = (const uint4*)(g_Vtlp + (size_t)b * 64 * 1024);

    for (int kb = kb0; kb <= kb1; kb++) {
        #pragma unroll
        for (int i = 0; i < 4; i++) {
            int idx = tid + (i << 7);    // 0..511
            int r = idx >> 3, q = idx & 7;
            *(uint4*)&Kh[r * KPITCH + q * 8]  = Khg4[(size_t)(kb * 64 + r) * 8 + q];
            *(uint4*)&Kl[r * KPITCH + q * 8]  = Klg4[(size_t)(kb * 64 + r) * 8 + q];
            *(uint4*)&Vth[r * KPITCH + q * 8] = Vhg4[(size_t)r * 256 + kb * 8 + q];
            *(uint4*)&Vtl[r * KPITCH + q * 8] = Vlg4[(size_t)r * 256 + kb * 8 + q];
        }
        __syncthreads();

        // S = Q K^T (3-term split).
        float s[8][4] = {};
        #pragma unroll
        for (int nt = 0; nt < 8; nt++) {
            #pragma unroll
            for (int kt = 0; kt < 4; kt++) {
                int cb = (nt * 8 + grow) * KPITCH + kt * 16 + tg * 2;
                uint32_t bh0 = lds32(Kh + cb), bh1 = lds32(Kh + cb + 8);
                uint32_t bl0 = lds32(Kl + cb), bl1 = lds32(Kl + cb + 8);
                mma_bf16(s[nt], qh[kt][0], qh[kt][1], qh[kt][2], qh[kt][3], bh0, bh1);
                mma_bf16(s[nt], qh[kt][0], qh[kt][1], qh[kt][2], qh[kt][3], bl0, bl1);
                mma_bf16(s[nt], ql[kt][0], ql[kt][1], ql[kt][2], ql[kt][3], bh0, bh1);
            }
        }

        // scale + causal mask (only the diagonal tile needs masking).
        if (kb == qb) {
            #pragma unroll
            for (int nt = 0; nt < 8; nt++) {
                int kc = kb * 64 + nt * 8 + tg * 2;
                s[nt][0] = (kc     > qr0)     ? -1e30f : s[nt][0] * SCL;
                s[nt][1] = (kc + 1 > qr0)     ? -1e30f : s[nt][1] * SCL;
                s[nt][2] = (kc     > qr0 + 8) ? -1e30f : s[nt][2] * SCL;
                s[nt][3] = (kc + 1 > qr0 + 8) ? -1e30f : s[nt][3] * SCL;
            }
        } else {
            #pragma unroll
            for (int nt = 0; nt < 8; nt++) {
                s[nt][0] *= SCL; s[nt][1] *= SCL;
                s[nt][2] *= SCL; s[nt][3] *= SCL;
            }
        }

        // online softmax (base-2).
        float mx0 = -1e30f, mx1 = -1e30f;
        #pragma unroll
        for (int nt = 0; nt < 8; nt++) {
            mx0 = fmaxf(mx0, fmaxf(s[nt][0], s[nt][1]));
            mx1 = fmaxf(mx1, fmaxf(s[nt][2], s[nt][3]));
        }
        mx0 = fmaxf(mx0, __shfl_xor_sync(0xffffffffu, mx0, 1));
        mx0 = fmaxf(mx0, __shfl_xor_sync(0xffffffffu, mx0, 2));
        mx1 = fmaxf(mx1, __shfl_xor_sync(0xffffffffu, mx1, 1));
        mx1 = fmaxf(mx1, __shfl_xor_sync(0xffffffffu, mx1, 2));
        float nm0 = fmaxf(m0, mx0), nm1 = fmaxf(m1, mx1);
        float a0 = exp2_fast(m0 - nm0), a1 = exp2_fast(m1 - nm1);
        m0 = nm0; m1 = nm1;

        float rs0 = 0.0f, rs1 = 0.0f;
        #pragma unroll
        for (int nt = 0; nt < 8; nt++) {
            float p0 = exp2_fast(s[nt][0] - nm0);
            float p1 = exp2_fast(s[nt][1] - nm0);
            float p2 = exp2_fast(s[nt][2] - nm1);
            float p3 = exp2_fast(s[nt][3] - nm1);
            s[nt][0] = p0; s[nt][1] = p1; s[nt][2] = p2; s[nt][3] = p3;
            rs0 += p0 + p1;
            rs1 += p2 + p3;
        }
        rs0 += __shfl_xor_sync(0xffffffffu, rs0, 1);
        rs0 += __shfl_xor_sync(0xffffffffu, rs0, 2);
        rs1 += __shfl_xor_sync(0xffffffffu, rs1, 1);
        rs1 += __shfl_xor_sync(0xffffffffu, rs1, 2);
        l0 = l0 * a0 + rs0;
        l1 = l1 * a1 + rs1;
        #pragma unroll
        for (int nt = 0; nt < 8; nt++) {
            o[nt][0] *= a0; o[nt][1] *= a0;
            o[nt][2] *= a1; o[nt][3] *= a1;
        }

        // O += P V (3-term split).
        #pragma unroll
        for (int kt = 0; kt < 4; kt++) {
            uint32_t ph[4], pl[4];
            tsplit2(s[2 * kt][0],     s[2 * kt][1],     ph[0], pl[0]);
            tsplit2(s[2 * kt][2],     s[2 * kt][3],     ph[1], pl[1]);
            tsplit2(s[2 * kt + 1][0], s[2 * kt + 1][1], ph[2], pl[2]);
            tsplit2(s[2 * kt + 1][2], s[2 * kt + 1][3], ph[3], pl[3]);
            #pragma unroll
            for (int nt = 0; nt < 8; nt++) {
                int cb = (nt * 8 + grow) * KPITCH + kt * 16 + tg * 2;
                uint32_t bh0 = lds32(Vth + cb), bh1 = lds32(Vth + cb + 8);
                uint32_t bl0 = lds32(Vtl + cb), bl1 = lds32(Vtl + cb + 8);
                mma_bf16(o[nt], ph[0], ph[1], ph[2], ph[3], bh0, bh1);
                mma_bf16(o[nt], ph[0], ph[1], ph[2], ph[3], bl0, bl1);
                mma_bf16(o[nt], pl[0], pl[1], pl[2], pl[3], bh0, bh1);
            }
        }
        __syncthreads();
    }

    // ---- write partial (unnormalized O + m,l per row).
    const size_t unit = ((size_t)b * 32 + qb) * 4 + ci;
    float* pO = g_pO + unit * 4096 + (size_t)(wm * 16) * 64;
    #pragma unroll
    for (int nt = 0; nt < 8; nt++) {
        *(float2*)(pO + grow * 64 + nt * 8 + tg * 2) = make_float2(o[nt][0], o[nt][1]);
        *(float2*)(pO + (grow + 8) * 64 + nt * 8 + tg * 2) = make_float2(o[nt][2], o[nt][3]);
    }
    if (tg == 0) {
        g_pm[unit * 64 + wm * 16 + grow]     = m0;
        g_pm[unit * 64 + wm * 16 + grow + 8] = m1;
        g_pl[unit * 64 + wm * 16 + grow]     = l0;
        g_pl[unit * 64 + wm * 16 + grow + 8] = l1;
    }
}

// ---------------------------------------------------------------------------
// Kernel 2b: combine partials. Grid (32, 8), 256 threads.
// Thread t: row r = t>>2, cols [(t&3)*16, +16).
// ---------------------------------------------------------------------------
__global__ __launch_bounds__(256) void attn_combine(float* __restrict__ Out)
{
    const int qb = blockIdx.x;
    const int b  = blockIdx.y;
    const int tid = threadIdx.x;
    const int r = tid >> 2;
    const int c0 = (tid & 3) * 16;
    const int nc = (qb >> 3) + 1;

    const size_t ubase = ((size_t)b * 32 + qb) * 4;

    float mi[4], li[4];
    float M = -1e30f;
    #pragma unroll 4
    for (int i = 0; i < nc; i++) {
        mi[i] = g_pm[(ubase + i) * 64 + r];
        li[i] = g_pl[(ubase + i) * 64 + r];
        M = fmaxf(M, mi[i]);
    }

    float acc[16] = {};
    float L = 0.0f;
    #pragma unroll 4
    for (int i = 0; i < nc; i++) {
        float al = exp2_fast(mi[i] - M);
        L += al * li[i];
        const float* pO = g_pO + (ubase + i) * 4096 + (size_t)r * 64 + c0;
        #pragma unroll
        for (int q = 0; q < 4; q++) {
            float4 v = *(const float4*)(pO + q * 4);
            acc[q * 4 + 0] += al * v.x;
            acc[q * 4 + 1] += al * v.y;
            acc[q * 4 + 2] += al * v.z;
            acc[q * 4 + 3] += al * v.w;
        }
    }

    float inv = 1.0f / L;
    float* Og = Out + (size_t)(b * SS + qb * 64 + r) * HH + c0;
    #pragma unroll
    for (int q = 0; q < 4; q++) {
        *(float4*)(Og + q * 4) = make_float4(acc[q * 4 + 0] * inv, acc[q * 4 + 1] * inv,
                                             acc[q * 4 + 2] * inv, acc[q * 4 + 3] * inv);
    }
}

// ---------------------------------------------------------------------------
extern "C" void kernel_launch(void* const* d_in, const int* in_sizes, int n_in,
                              void* d_out, int out_size)
{
    const float* x  = (const float*)d_in[0];
    const float* Wq = (const float*)d_in[1];
    const float* Wk = (const float*)d_in[2];
    const float* Wv = (const float*)d_in[3];
    float* out = (float*)d_out;
    (void)in_sizes; (void)n_in; (void)out_size;

    prep_w<<<768, 256>>>(Wq, Wk, Wv);
    qkv_mma<<<(BB * SS) / 128, 256>>>(x);
    prep_vt<<<dim3(SS / 64, BB), 256>>>();
    attn_part<<<dim3(80, BB), 128>>>(out);
    attn_combine<<<dim3(32, BB), 256>>>(out);
}